// round 2
// baseline (speedup 1.0000x reference)
#include <cuda_runtime.h>
#include <cstdint>

// SoftNormalShader: gather vertex normals + barycentric interp + softmax RGB blend.
// Shapes: N=4,H=512,W=512,K=8 ; V=50000, F=100000.
// Inputs (metadata order) — NOTE: JAX default x64-disabled => int arrays are int32:
//   0: verts_normals (V,3)        float32
//   1: bary_coords  (N,H,W,K,3)   float32
//   2: dists        (N,H,W,K)     float32
//   3: zbuf         (N,H,W,K)     float32
//   4: faces        (F,3)         int32
//   5: pix_to_face  (N,H,W,K)     int32
// Output: (N,H,W,4) float32

#define KSAMP 8
#define SIGMA_F   1e-4f
#define GAMMA_F   1e-4f
#define ZNEAR_F   1.0f
#define ZFAR_F    100.0f
#define EPS_F     1e-10f

__global__ __launch_bounds__(256, 8)
void soft_normal_shader_kernel(
    const float* __restrict__ vn,      // (V,3)
    const float* __restrict__ bary,    // (P,8,3)
    const float* __restrict__ dists,   // (P,8)
    const float* __restrict__ zbuf,    // (P,8)
    const int*   __restrict__ faces,   // (F,3)
    const int*   __restrict__ p2f,     // (P,8)
    float4*      __restrict__ out,     // (P,) rgba
    int npix)
{
    int pix = blockIdx.x * blockDim.x + threadIdx.x;
    if (pix >= npix) return;

    const long long base = (long long)pix * KSAMP;

    // ---- vectorized per-pixel loads ----
    float dk[KSAMP], zk[KSAMP];
    {
        const float4* dp = reinterpret_cast<const float4*>(dists + base);
        const float4* zp = reinterpret_cast<const float4*>(zbuf  + base);
        float4 d0 = __ldg(dp + 0), d1 = __ldg(dp + 1);
        float4 z0 = __ldg(zp + 0), z1 = __ldg(zp + 1);
        dk[0]=d0.x; dk[1]=d0.y; dk[2]=d0.z; dk[3]=d0.w;
        dk[4]=d1.x; dk[5]=d1.y; dk[6]=d1.z; dk[7]=d1.w;
        zk[0]=z0.x; zk[1]=z0.y; zk[2]=z0.z; zk[3]=z0.w;
        zk[4]=z1.x; zk[5]=z1.y; zk[6]=z1.z; zk[7]=z1.w;
    }

    int fidx[KSAMP];
    {
        const int4* pp = reinterpret_cast<const int4*>(p2f + base);
        int4 a = __ldg(pp + 0), b = __ldg(pp + 1);
        fidx[0]=a.x; fidx[1]=a.y; fidx[2]=a.z; fidx[3]=a.w;
        fidx[4]=b.x; fidx[5]=b.y; fidx[6]=b.z; fidx[7]=b.w;
    }

    float bk[KSAMP][3];
    {
        const float4* bp = reinterpret_cast<const float4*>(bary + base * 3);
        float4 b[6];
        #pragma unroll
        for (int i = 0; i < 6; i++) b[i] = __ldg(bp + i);
        const float* bf = reinterpret_cast<const float*>(b);
        #pragma unroll
        for (int k = 0; k < KSAMP; k++) {
            bk[k][0] = bf[3*k + 0];
            bk[k][1] = bf[3*k + 1];
            bk[k][2] = bf[3*k + 2];
        }
    }

    // ---- pass 1: prob_map, z_inv, z_inv_max, alpha ----
    float pm[KSAMP], zi[KSAMP];
    float zmax = -1e30f;
    float one_minus_prod = 1.0f;
    const float inv_range = 1.0f / (ZFAR_F - ZNEAR_F);
    #pragma unroll
    for (int k = 0; k < KSAMP; k++) {
        bool valid = fidx[k] >= 0;
        // sigmoid(-d/SIGMA) = 1/(1+exp(d/SIGMA))
        float p = valid ? (1.0f / (1.0f + __expf(dk[k] * (1.0f / SIGMA_F)))) : 0.0f;
        pm[k] = p;
        one_minus_prod *= (1.0f - p);
        zi[k] = valid ? (ZFAR_F - zk[k]) * inv_range : 0.0f;
        zmax = fmaxf(zmax, zi[k]);
    }

    // ---- pass 2: weights + gathered interpolated normals (skip if w == 0) ----
    // exp((zi-zmax)/GAMMA) underflows to exactly 0 unless zi is within ~9e-3 of
    // zmax (zi spread is O(1)), so typically only 1 of 8 samples gathers.
    float wsum = 0.0f;
    float accr = 0.0f, accg = 0.0f, accb = 0.0f;
    #pragma unroll
    for (int k = 0; k < KSAMP; k++) {
        float w = pm[k] * __expf((zi[k] - zmax) * (1.0f / GAMMA_F));
        wsum += w;
        if (w > 0.0f) {
            const int* fr = faces + (long long)fidx[k] * 3;
            int v0 = __ldg(fr + 0);
            int v1 = __ldg(fr + 1);
            int v2 = __ldg(fr + 2);
            const float* n0 = vn + (long long)v0 * 3;
            const float* n1 = vn + (long long)v1 * 3;
            const float* n2 = vn + (long long)v2 * 3;
            float b0 = bk[k][0], b1 = bk[k][1], b2 = bk[k][2];
            float cr = b0 * __ldg(n0 + 0) + b1 * __ldg(n1 + 0) + b2 * __ldg(n2 + 0);
            float cg = b0 * __ldg(n0 + 1) + b1 * __ldg(n1 + 1) + b2 * __ldg(n2 + 1);
            float cb = b0 * __ldg(n0 + 2) + b1 * __ldg(n1 + 2) + b2 * __ldg(n2 + 2);
            accr += w * cr;
            accg += w * cg;
            accb += w * cb;
        }
    }

    // ---- blend ----
    float delta = fmaxf(__expf((EPS_F - zmax) * (1.0f / GAMMA_F)), EPS_F);
    float inv_denom = 1.0f / (wsum + delta);
    float4 o;
    o.x = (accr + delta) * inv_denom;   // background = (1,1,1)
    o.y = (accg + delta) * inv_denom;
    o.z = (accb + delta) * inv_denom;
    o.w = 1.0f - one_minus_prod;        // 1 - alpha
    out[pix] = o;
}

extern "C" void kernel_launch(void* const* d_in, const int* in_sizes, int n_in,
                              void* d_out, int out_size)
{
    const float* vn    = (const float*)d_in[0];
    const float* bary  = (const float*)d_in[1];
    const float* dists = (const float*)d_in[2];
    const float* zbuf  = (const float*)d_in[3];
    const int*   faces = (const int*)d_in[4];
    const int*   p2f   = (const int*)d_in[5];
    float4*      out   = (float4*)d_out;

    int npix = in_sizes[2] / KSAMP;   // N*H*W
    int threads = 256;
    int blocks = (npix + threads - 1) / threads;
    soft_normal_shader_kernel<<<blocks, threads>>>(vn, bary, dists, zbuf, faces, p2f, out, npix);
}

// round 3
// speedup vs baseline: 1.4493x; 1.4493x over previous
#include <cuda_runtime.h>
#include <cstdint>

// SoftNormalShader: gather vertex normals + barycentric interp + softmax RGB blend.
// Shapes: N=4,H=512,W=512,K=8 ; V=50000, F=100000.
// Inputs (JAX x64 disabled => int arrays are int32):
//   0: verts_normals (V,3)        float32
//   1: bary_coords  (N,H,W,K,3)   float32   <-- loaded LAZILY (only where weight>0)
//   2: dists        (N,H,W,K)     float32
//   3: zbuf         (N,H,W,K)     float32
//   4: faces        (F,3)         int32
//   5: pix_to_face  (N,H,W,K)     int32
// Output: (N,H,W,4) float32

#define KSAMP 8
#define SIGMA_F   1e-4f
#define GAMMA_F   1e-4f
#define ZNEAR_F   1.0f
#define ZFAR_F    100.0f
#define EPS_F     1e-10f

__global__ __launch_bounds__(256, 8)
void soft_normal_shader_kernel(
    const float* __restrict__ vn,      // (V,3)
    const float* __restrict__ bary,    // (P,8,3)
    const float* __restrict__ dists,   // (P,8)
    const float* __restrict__ zbuf,    // (P,8)
    const int*   __restrict__ faces,   // (F,3)
    const int*   __restrict__ p2f,     // (P,8)
    float4*      __restrict__ out,     // (P,) rgba
    int npix)
{
    int pix = blockIdx.x * blockDim.x + threadIdx.x;
    if (pix >= npix) return;

    const long long base = (long long)pix * KSAMP;

    // ---- vectorized per-pixel streaming loads (dists, zbuf, p2f) ----
    float dk[KSAMP], zk[KSAMP];
    int fidx[KSAMP];
    {
        const float4* dp = reinterpret_cast<const float4*>(dists + base);
        const float4* zp = reinterpret_cast<const float4*>(zbuf  + base);
        const int4*   pp = reinterpret_cast<const int4*>(p2f + base);
        float4 d0 = __ldg(dp + 0), d1 = __ldg(dp + 1);
        float4 z0 = __ldg(zp + 0), z1 = __ldg(zp + 1);
        int4   a  = __ldg(pp + 0), b  = __ldg(pp + 1);
        dk[0]=d0.x; dk[1]=d0.y; dk[2]=d0.z; dk[3]=d0.w;
        dk[4]=d1.x; dk[5]=d1.y; dk[6]=d1.z; dk[7]=d1.w;
        zk[0]=z0.x; zk[1]=z0.y; zk[2]=z0.z; zk[3]=z0.w;
        zk[4]=z1.x; zk[5]=z1.y; zk[6]=z1.z; zk[7]=z1.w;
        fidx[0]=a.x; fidx[1]=a.y; fidx[2]=a.z; fidx[3]=a.w;
        fidx[4]=b.x; fidx[5]=b.y; fidx[6]=b.z; fidx[7]=b.w;
    }

    // ---- pass 1: prob_map, z_inv, z_inv_max, alpha ----
    float pm[KSAMP], zi[KSAMP];
    float zmax = -1e30f;
    float one_minus_prod = 1.0f;
    const float inv_range = 1.0f / (ZFAR_F - ZNEAR_F);
    #pragma unroll
    for (int k = 0; k < KSAMP; k++) {
        bool valid = fidx[k] >= 0;
        // sigmoid(-d/SIGMA) = 1/(1+exp(d/SIGMA))
        float p = valid ? (1.0f / (1.0f + __expf(dk[k] * (1.0f / SIGMA_F)))) : 0.0f;
        pm[k] = p;
        one_minus_prod *= (1.0f - p);
        zi[k] = valid ? (ZFAR_F - zk[k]) * inv_range : 0.0f;
        zmax = fmaxf(zmax, zi[k]);
    }

    // ---- pass 2: weights + lazy gathers (bary + normals) only where w > 0 ----
    // exp((zi-zmax)/GAMMA) underflows to exactly 0 unless zi is within ~9e-3 of
    // zmax; zbuf is uniform over [1,100], so typically only 1 of 8 samples
    // carries weight. Everything multiplied by w==0 is skipped bit-exactly.
    float wsum = 0.0f;
    float accr = 0.0f, accg = 0.0f, accb = 0.0f;
    #pragma unroll
    for (int k = 0; k < KSAMP; k++) {
        float w = pm[k] * __expf((zi[k] - zmax) * (1.0f / GAMMA_F));
        wsum += w;
        if (w > 0.0f) {
            // lazy barycentric load (12B) — independent of faces/vn chain
            const float* bp = bary + (base + k) * 3;
            float b0 = __ldg(bp + 0);
            float b1 = __ldg(bp + 1);
            float b2 = __ldg(bp + 2);
            // face vertex indices (3 x int32, contiguous)
            const int* fr = faces + (long long)fidx[k] * 3;
            int v0 = __ldg(fr + 0);
            int v1 = __ldg(fr + 1);
            int v2 = __ldg(fr + 2);
            const float* n0 = vn + (long long)v0 * 3;
            const float* n1 = vn + (long long)v1 * 3;
            const float* n2 = vn + (long long)v2 * 3;
            float cr = b0 * __ldg(n0 + 0) + b1 * __ldg(n1 + 0) + b2 * __ldg(n2 + 0);
            float cg = b0 * __ldg(n0 + 1) + b1 * __ldg(n1 + 1) + b2 * __ldg(n2 + 1);
            float cb = b0 * __ldg(n0 + 2) + b1 * __ldg(n1 + 2) + b2 * __ldg(n2 + 2);
            accr += w * cr;
            accg += w * cg;
            accb += w * cb;
        }
    }

    // ---- blend ----
    float delta = fmaxf(__expf((EPS_F - zmax) * (1.0f / GAMMA_F)), EPS_F);
    float inv_denom = 1.0f / (wsum + delta);
    float4 o;
    o.x = (accr + delta) * inv_denom;   // background = (1,1,1)
    o.y = (accg + delta) * inv_denom;
    o.z = (accb + delta) * inv_denom;
    o.w = 1.0f - one_minus_prod;        // 1 - alpha
    out[pix] = o;
}

extern "C" void kernel_launch(void* const* d_in, const int* in_sizes, int n_in,
                              void* d_out, int out_size)
{
    const float* vn    = (const float*)d_in[0];
    const float* bary  = (const float*)d_in[1];
    const float* dists = (const float*)d_in[2];
    const float* zbuf  = (const float*)d_in[3];
    const int*   faces = (const int*)d_in[4];
    const int*   p2f   = (const int*)d_in[5];
    float4*      out   = (float4*)d_out;

    int npix = in_sizes[2] / KSAMP;   // N*H*W
    int threads = 256;
    int blocks = (npix + threads - 1) / threads;
    soft_normal_shader_kernel<<<blocks, threads>>>(vn, bary, dists, zbuf, faces, p2f, out, npix);
}